// round 2
// baseline (speedup 1.0000x reference)
#include <cuda_runtime.h>
#include <cuda_bf16.h>
#include <math.h>
#include <stdint.h>

#define NN 8192
#define NB 1024
#define NM 256

// ---------------- device scratch (static, no allocation) ----------------
__device__ float g_z[128];
__device__ float g_v0[512];
__device__ float g_Ppsm[NM * 512];
__device__ float g_psmWhh[512 * 128];     // packed [j][r]
__device__ float g_Hseq[NM * 128];
__device__ float g_mps[NM * 128];
__device__ int   g_bidx[NN];
__device__ int   g_midx[NN];
__device__ int   g_startf[NN];
__device__ float g_POn[NN * 1024];
__device__ float g_POb[NB * 1024];
__device__ float g_POm[NM * 1024];
__device__ float g_PTb[NB * 1024];
__device__ float g_PTm[NM * 1024];
__device__ float g_WhhO[8 * 64 * 128 * 4]; // [c][j4][rl][jj]
__device__ float g_WhhT[8 * 64 * 128 * 4];
__device__ float g_WseqO[8 * 128 * 11];    // [c*128+rl][k]
__device__ float g_WseqT[8 * 128 * 11];

__device__ __forceinline__ float sigm(float x) { return 1.0f / (1.0f + __expf(-x)); }

__device__ __forceinline__ void st_cluster_f32(uint32_t local_addr, uint32_t rank, float v) {
    uint32_t remote;
    asm volatile("mapa.shared::cluster.u32 %0, %1, %2;" : "=r"(remote) : "r"(local_addr), "r"(rank));
    asm volatile("st.shared::cluster.f32 [%0], %1;" :: "r"(remote), "f"(v) : "memory");
}
__device__ __forceinline__ void cluster_sync_all() {
    asm volatile("barrier.cluster.arrive.aligned;" ::: "memory");
    asm volatile("barrier.cluster.wait.aligned;" ::: "memory");
}

// ---------------- generic tiled GEMM: C[M][N] (+)= X[M][K] @ W[:, wofs:wofs+K]^T (+bias) ----
// M%64==0, N%64==0, K arbitrary
__global__ void k_gemm(const float* __restrict__ X, int ldx,
                       const float* __restrict__ W, int ldw, int wofs,
                       float* __restrict__ C, int M, int N, int K,
                       const float* __restrict__ bias, int accum)
{
    __shared__ float Xs[16][65];
    __shared__ float Ws[16][65];
    int tid = threadIdx.x;
    int tx = tid & 15, ty = tid >> 4;
    int n0 = blockIdx.x * 64, m0 = blockIdx.y * 64;
    float acc[4][4];
#pragma unroll
    for (int i = 0; i < 4; i++)
#pragma unroll
        for (int j = 0; j < 4; j++) acc[i][j] = 0.f;

    for (int k0 = 0; k0 < K; k0 += 16) {
        for (int i = tid; i < 1024; i += 256) {
            int mm = i >> 4, kk = i & 15;
            int k = k0 + kk;
            Xs[kk][mm] = (k < K) ? X[(size_t)(m0 + mm) * ldx + k] : 0.f;
            Ws[kk][mm] = (k < K) ? W[(size_t)(n0 + mm) * ldw + wofs + k] : 0.f;
        }
        __syncthreads();
#pragma unroll
        for (int kk = 0; kk < 16; kk++) {
            float a[4], b[4];
#pragma unroll
            for (int i = 0; i < 4; i++) a[i] = Xs[kk][ty * 4 + i];
#pragma unroll
            for (int j = 0; j < 4; j++) b[j] = Ws[kk][tx * 4 + j];
#pragma unroll
            for (int i = 0; i < 4; i++)
#pragma unroll
                for (int j = 0; j < 4; j++) acc[i][j] += a[i] * b[j];
        }
        __syncthreads();
    }
#pragma unroll
    for (int i = 0; i < 4; i++) {
        int m = m0 + ty * 4 + i;
#pragma unroll
        for (int j = 0; j < 4; j++) {
            int n = n0 + tx * 4 + j;
            float v = acc[i][j];
            if (bias) v += bias[n];
            size_t o = (size_t)m * N + n;
            if (accum) v += C[o];
            C[o] = v;
        }
    }
}

// ---------------- small prep kernels ----------------
__global__ void k_style(const float* __restrict__ perf, const float* __restrict__ sveW,
                        const float* __restrict__ sveb)
{
    int r = threadIdx.x; // 128
    float s = sveb[r];
    for (int k = 0; k < 64; k++) s += sveW[r * 64 + k] * perf[k];
    g_z[r] = fmaxf(s, 0.f);
}

__global__ void k_v0(const float* __restrict__ psmWih, const float* __restrict__ psmb)
{
    int r = threadIdx.x; // 512
    float s = psmb[r];
    for (int k = 0; k < 128; k++) s += psmWih[r * 384 + k] * g_z[k];
    g_v0[r] = s;
}

__global__ void k_idx(const int* __restrict__ bn, const int* __restrict__ mn)
{
    int i = blockIdx.x * 256 + threadIdx.x;
    if (i >= NN) return;
    int b0 = bn[0], m0 = mn[0];
    g_bidx[i] = bn[i] - b0;
    g_midx[i] = mn[i] - m0;
    g_startf[i] = (i == 0) ? 1 : ((bn[i] > bn[i - 1]) ? 1 : 0);
}

__global__ void k_pack_psm(const float* __restrict__ psmWhh)
{
    int idx = blockIdx.x * 256 + threadIdx.x; // 65536
    int r = idx & 511, j = idx >> 9;
    g_psmWhh[idx] = psmWhh[r * 128 + j];     // idx = j*512 + r
}

__global__ void k_pack_whh(const float* __restrict__ whhO, const float* __restrict__ whhT)
{
    int idx = blockIdx.x * 256 + threadIdx.x; // 262144
    int jj = idx & 3, rl = (idx >> 2) & 127, j4 = (idx >> 9) & 63, c = idx >> 15;
    int grow = (rl >> 5) * 256 + c * 32 + (rl & 31);
    int col = j4 * 4 + jj;
    g_WhhO[idx] = whhO[grow * 256 + col];
    g_WhhT[idx] = whhT[grow * 256 + col];
}

__global__ void k_pack_wseq(const float* __restrict__ outWih, const float* __restrict__ tempoWih)
{
    int idx = blockIdx.x * 256 + threadIdx.x;
    if (idx >= 8 * 128 * 11) return;
    int k = idx % 11;
    int rc = idx / 11;              // c*128 + rl
    int rl = rc & 127, c = rc >> 7;
    int grow = (rl >> 5) * 256 + c * 32 + (rl & 31);
    g_WseqO[idx] = outWih[(size_t)grow * 1419 + 1280 + k];
    int col = (k == 0) ? 768 : (776 + k);
    g_WseqT[idx] = tempoWih[(size_t)grow * 915 + col];
}

// ---------------- psm LSTM over 256 measures (one CTA, 512 threads) ----------------
__global__ void __launch_bounds__(512, 1) k_psm_seq()
{
    __shared__ float h[128], cst[128];
    __shared__ float part[4][512];
    __shared__ float gate[512];
    int t = threadIdx.x;
    int a = t & 127, jg = t >> 7;
    if (t < 128) { h[t] = 0.f; cst[t] = 0.f; }
    __syncthreads();
    for (int m = 0; m < NM; m++) {
        float a0 = 0, a1 = 0, a2 = 0, a3 = 0;
#pragma unroll 4
        for (int jj = 0; jj < 32; jj++) {
            int j = jg * 32 + jj;
            float4 w = *(const float4*)(g_psmWhh + j * 512 + 4 * a);
            float hv = h[j];
            a0 += w.x * hv; a1 += w.y * hv; a2 += w.z * hv; a3 += w.w * hv;
        }
        part[jg][4 * a + 0] = a0; part[jg][4 * a + 1] = a1;
        part[jg][4 * a + 2] = a2; part[jg][4 * a + 3] = a3;
        __syncthreads();
        {
            float s = g_Ppsm[m * 512 + t] + g_v0[t];
#pragma unroll
            for (int gg = 0; gg < 4; gg++) s += part[gg][t];
            gate[t] = s;
        }
        __syncthreads();
        if (t < 128) {
            float cn = sigm(gate[128 + t]) * cst[t] + sigm(gate[t]) * tanhf(gate[256 + t]);
            cst[t] = cn;
            float hn = sigm(gate[384 + t]) * tanhf(cn);
            h[t] = hn;
            g_Hseq[m * 128 + t] = hn;
        }
        __syncthreads();
    }
}

// ---------------- sequential decoder: 8-CTA cluster, 512 thr/CTA ----------------
__global__ void __cluster_dims__(8, 1, 1) __launch_bounds__(512, 1)
k_seq(const float* __restrict__ fcW, const float* __restrict__ fcb,
      const float* __restrict__ tfcW, const float* __restrict__ tfcb,
      const float* __restrict__ attW, const float* __restrict__ attb,
      const float* __restrict__ attc, float* __restrict__ out)
{
    __shared__ float hbuf[2][256];
    __shared__ float thbuf[2][256];
    __shared__ float part[4][128];
    __shared__ float partT[4][128];
    __shared__ float presm[128], presmT[128];
    __shared__ float WsO[128][13], WsT[128][13];
    __shared__ float fcWs[10][256];
    __shared__ float tfcWs[256];
    __shared__ float attWs[10][10], attbs[10], attcs[10], fcbs[10];
    __shared__ float result_s[12];
    __shared__ float buf_s[8][12];
    __shared__ float o_sm[12];
    __shared__ float prev_out_s[12];
    __shared__ float prevT_s;
    __shared__ float wsoft[8];
    __shared__ float tfcb_s;

    const int t = threadIdx.x;
    uint32_t crank;
    asm("mov.u32 %0, %%cluster_ctarank;" : "=r"(crank));
    const int rl = t & 127, s = t >> 7;
    const int u = t & 31;

    // register-resident out-LSTM Whh slice: 64 weights / thread
    float w[64];
    {
        const float4* src = (const float4*)g_WhhO;
#pragma unroll
        for (int ii = 0; ii < 16; ii++) {
            float4 v = src[((int)crank * 64 + s * 16 + ii) * 128 + rl];
            w[4 * ii + 0] = v.x; w[4 * ii + 1] = v.y; w[4 * ii + 2] = v.z; w[4 * ii + 3] = v.w;
        }
    }
    if (t < 128) {
        for (int k = 0; k < 11; k++) {
            WsO[t][k] = g_WseqO[((int)crank * 128 + t) * 11 + k];
            WsT[t][k] = g_WseqT[((int)crank * 128 + t) * 11 + k];
        }
    }
    for (int i = t; i < 2560; i += 512) fcWs[i >> 8][i & 255] = fcW[i];
    if (t < 256) { tfcWs[t] = tfcW[t]; hbuf[0][t] = 0.f; thbuf[0][t] = 0.f; }
    if (t < 100) attWs[t / 10][t % 10] = attW[t];
    if (t < 10) { attbs[t] = attb[t]; attcs[t] = attc[t]; fcbs[t] = fcb[t]; }
    if (t < 12) { prev_out_s[t] = 0.f; result_s[t] = 0.f; }
    if (t < 96) buf_s[t / 12][t % 12] = 0.f;
    if (t == 0) { tfcb_s = tfcb[0]; prevT_s = 0.f; }
    __syncthreads();
    cluster_sync_all();

    float cst = 0.f;   // out-LSTM cell (threads 0..31)
    float tcst = 0.f;  // tempo cell   (threads 32..63)
    int cnt = 0, hp = 0, tp = 0;

    for (int n = 0; n < NN; n++) {
        const bool start = (g_startf[n] != 0);
        const int b = g_bidx[n], m = g_midx[n];

        if (start) {
            // ---- attention over previous beat's fc outputs (warp 0) ----
            if (t < 32) {
                if (u < 8) {
                    float sc = 0.f;
#pragma unroll
                    for (int j = 0; j < 10; j++) {
                        float a = attbs[j];
#pragma unroll
                        for (int k = 0; k < 10; k++) a += attWs[j][k] * buf_s[u][k];
                        sc += tanhf(a) * attcs[j];
                    }
                    float se = (u < cnt) ? sc : -1e30f;
                    float mx = se;
#pragma unroll
                    for (int off = 4; off; off >>= 1) mx = fmaxf(mx, __shfl_xor_sync(0xffu, mx, off));
                    float e = __expf(se - mx);
                    float sm = e;
#pragma unroll
                    for (int off = 4; off; off >>= 1) sm += __shfl_xor_sync(0xffu, sm, off);
                    wsoft[u] = e / sm;
                }
                __syncwarp();
                if (u < 10) {
                    float r = 0.f;
                    if (cnt > 0) {
#pragma unroll
                        for (int p = 0; p < 8; p++) r += wsoft[p] * buf_s[p][u];
                    }
                    result_s[u] = r;
                }
            }
            cnt = 0;
            __syncthreads();
        }

        // ---- phase C: matvecs ----
        float pv = 0.f, pvT = 0.f;
        if (t < 128) {
            int grow = (t >> 5) * 256 + (int)crank * 32 + (t & 31);
            pv = g_POn[n * 1024 + grow] + g_POb[b * 1024 + grow] + g_POm[m * 1024 + grow];
            if (start) pvT = g_PTb[b * 1024 + grow] + g_PTm[m * 1024 + grow];
        }
        float acc = 0.f;
        {
            const float4* hb4 = (const float4*)hbuf[hp];
#pragma unroll
            for (int ii = 0; ii < 16; ii++) {
                float4 hv = hb4[s * 16 + ii];
                acc += w[4 * ii] * hv.x + w[4 * ii + 1] * hv.y + w[4 * ii + 2] * hv.z + w[4 * ii + 3] * hv.w;
            }
        }
        if (s == 0) {
#pragma unroll
            for (int k = 0; k < 11; k++) acc += WsO[rl][k] * prev_out_s[k];
        }
        part[s][rl] = acc;
        if (start) {
            float accT = 0.f;
            const float4* wt4 = (const float4*)g_WhhT;
            const float4* th4 = (const float4*)thbuf[tp];
#pragma unroll 4
            for (int ii = 0; ii < 16; ii++) {
                float4 wv = wt4[((int)crank * 64 + s * 16 + ii) * 128 + rl];
                float4 hv = th4[s * 16 + ii];
                accT += wv.x * hv.x + wv.y * hv.y + wv.z * hv.z + wv.w * hv.w;
            }
            if (s == 0) {
                accT += WsT[rl][0] * prevT_s;
#pragma unroll
                for (int k = 0; k < 10; k++) accT += WsT[rl][1 + k] * result_s[k];
            }
            partT[s][rl] = accT;
            if (t < 128) presmT[t] = pvT;
        }
        if (t < 128) presm[t] = pv;
        __syncthreads();

        // ---- phase D: gates + activations + DSMEM broadcast ----
        if (t < 32) {
            float gi = presm[u]      + part[0][u]      + part[1][u]      + part[2][u]      + part[3][u];
            float gf = presm[u + 32] + part[0][u + 32] + part[1][u + 32] + part[2][u + 32] + part[3][u + 32];
            float gg = presm[u + 64] + part[0][u + 64] + part[1][u + 64] + part[2][u + 64] + part[3][u + 64];
            float go = presm[u + 96] + part[0][u + 96] + part[1][u + 96] + part[2][u + 96] + part[3][u + 96];
            float cn = sigm(gf) * cst + sigm(gi) * tanhf(gg);
            cst = cn;
            float hn = sigm(go) * tanhf(cn);
            uint32_t la = (uint32_t)__cvta_generic_to_shared(&hbuf[hp ^ 1][(int)crank * 32 + u]);
#pragma unroll
            for (int r = 0; r < 8; r++) st_cluster_f32(la, r, hn);
        } else if (start && t < 64) {
            float gi = presmT[u]      + partT[0][u]      + partT[1][u]      + partT[2][u]      + partT[3][u];
            float gf = presmT[u + 32] + partT[0][u + 32] + partT[1][u + 32] + partT[2][u + 32] + partT[3][u + 32];
            float gg = presmT[u + 64] + partT[0][u + 64] + partT[1][u + 64] + partT[2][u + 64] + partT[3][u + 64];
            float go = presmT[u + 96] + partT[0][u + 96] + partT[1][u + 96] + partT[2][u + 96] + partT[3][u + 96];
            float cn = sigm(gf) * tcst + sigm(gi) * tanhf(gg);
            tcst = cn;
            float hn = sigm(go) * tanhf(cn);
            uint32_t la = (uint32_t)__cvta_generic_to_shared(&thbuf[tp ^ 1][(int)crank * 32 + u]);
#pragma unroll
            for (int r = 0; r < 8; r++) st_cluster_f32(la, r, hn);
        }
        cluster_sync_all();

        // ---- phase E: fc outputs from the NEW hidden state ----
        {
            int wid = t >> 5;
            if (wid < 10) {
                float p = 0.f;
                const float* hnew = hbuf[hp ^ 1];
#pragma unroll
                for (int k = 0; k < 8; k++) p += fcWs[wid][k * 32 + u] * hnew[k * 32 + u];
#pragma unroll
                for (int off = 16; off; off >>= 1) p += __shfl_down_sync(0xffffffffu, p, off);
                if (u == 0) o_sm[wid] = p + fcbs[wid];
            } else if (start && wid == 10) {
                float p = 0.f;
                const float* tn = thbuf[tp ^ 1];
#pragma unroll
                for (int k = 0; k < 8; k++) p += tfcWs[k * 32 + u] * tn[k * 32 + u];
#pragma unroll
                for (int off = 16; off; off >>= 1) p += __shfl_down_sync(0xffffffffu, p, off);
                if (u == 0) prevT_s = p + tfcb_s;
            }
        }
        __syncthreads();

        // ---- phase F: commit outputs / recurrent small state ----
        if (t < 10) buf_s[cnt][t] = o_sm[t];
        if (t < 11) {
            float v = (t == 0) ? prevT_s : o_sm[t - 1];
            prev_out_s[t] = v;
            if (crank == 0) out[n * 11 + t] = v;
        }
        cnt++;
        hp ^= 1;
        if (start) tp ^= 1;
        __syncthreads();
    }
}

// ---------------- host launcher ----------------
extern "C" void kernel_launch(void* const* d_in, const int* in_sizes, int n_in,
                              void* d_out, int out_size)
{
    const float* note     = (const float*)d_in[0];
    const float* beat     = (const float*)d_in[1];
    const float* meas     = (const float*)d_in[2];
    const float* perf     = (const float*)d_in[3];
    const float* res      = (const float*)d_in[4];
    const float* sveW     = (const float*)d_in[5];
    const float* sveb     = (const float*)d_in[6];
    const float* psmWih   = (const float*)d_in[7];
    const float* psmWhh   = (const float*)d_in[8];
    const float* psmb     = (const float*)d_in[9];
    const float* mpfW     = (const float*)d_in[10];
    const float* mpfb     = (const float*)d_in[11];
    const float* attW     = (const float*)d_in[12];
    const float* attb     = (const float*)d_in[13];
    const float* attc     = (const float*)d_in[14];
    const float* tempoWih = (const float*)d_in[15];
    const float* tempoWhh = (const float*)d_in[16];
    const float* tempob   = (const float*)d_in[17];
    const float* tfcW     = (const float*)d_in[18];
    const float* tfcb     = (const float*)d_in[19];
    const float* outWih   = (const float*)d_in[20];
    const float* outWhh   = (const float*)d_in[21];
    const float* outb     = (const float*)d_in[22];
    const float* fcW      = (const float*)d_in[23];
    const float* fcb      = (const float*)d_in[24];
    const int*   bn       = (const int*)d_in[25];
    const int*   mn       = (const int*)d_in[26];

    float *Ppsm, *Hseq, *mps, *POn, *POb, *POm, *PTb, *PTm;
    cudaGetSymbolAddress((void**)&Ppsm, g_Ppsm);
    cudaGetSymbolAddress((void**)&Hseq, g_Hseq);
    cudaGetSymbolAddress((void**)&mps,  g_mps);
    cudaGetSymbolAddress((void**)&POn,  g_POn);
    cudaGetSymbolAddress((void**)&POb,  g_POb);
    cudaGetSymbolAddress((void**)&POm,  g_POm);
    cudaGetSymbolAddress((void**)&PTb,  g_PTb);
    cudaGetSymbolAddress((void**)&PTm,  g_PTm);

    k_style<<<1, 128>>>(perf, sveW, sveb);
    k_v0<<<1, 512>>>(psmWih, psmb);
    k_idx<<<NN / 256, 256>>>(bn, mn);
    k_pack_whh<<<1024, 256>>>(outWhh, tempoWhh);
    k_pack_wseq<<<44, 256>>>(outWih, tempoWih);
    k_pack_psm<<<256, 256>>>(psmWhh);

    // psm input projection + psm LSTM + mps
    k_gemm<<<dim3(8, 4), 256>>>(meas, 256, psmWih, 384, 128, Ppsm, 256, 512, 256, nullptr, 0);
    k_psm_seq<<<1, 512>>>();
    k_gemm<<<dim3(2, 4), 256>>>(Hseq, 128, mpfW, 128, 0, mps, 256, 128, 128, mpfb, 0);

    // out-LSTM input projections
    k_gemm<<<dim3(16, 128), 256>>>(note, 512, outWih, 1419, 0,    POn, NN, 1024, 512, nullptr, 0);
    k_gemm<<<dim3(16, 16),  256>>>(beat, 512, outWih, 1419, 512,  POb, NB, 1024, 512, nullptr, 0);
    k_gemm<<<dim3(16, 4),   256>>>(meas, 256, outWih, 1419, 1024, POm, NM, 1024, 256, outb,    0);
    k_gemm<<<dim3(16, 4),   256>>>(mps,  128, outWih, 1419, 1291, POm, NM, 1024, 128, nullptr, 1);

    // tempo-LSTM input projections
    k_gemm<<<dim3(16, 16), 256>>>(beat, 512, tempoWih, 915, 0,   PTb, NB, 1024, 512, tempob,  0);
    k_gemm<<<dim3(16, 16), 256>>>(res,  8,   tempoWih, 915, 769, PTb, NB, 1024, 8,   nullptr, 1);
    k_gemm<<<dim3(16, 4),  256>>>(meas, 256, tempoWih, 915, 512, PTm, NM, 1024, 256, nullptr, 0);
    k_gemm<<<dim3(16, 4),  256>>>(mps,  128, tempoWih, 915, 787, PTm, NM, 1024, 128, nullptr, 1);

    // sequential decoder
    k_seq<<<8, 512>>>(fcW, fcb, tfcW, tfcb, attW, attb, attc, (float*)d_out);
}